// round 2
// baseline (speedup 1.0000x reference)
#include <cuda_runtime.h>
#include <cuda_bf16.h>
#include <cooperative_groups.h>

namespace cg = cooperative_groups;

// Problem dims
#define BB 32
#define SS 128
#define TT 127          // S-1 scan steps
#define KK 128
#define CC 256
#define CS 64           // concepts per CTA (cluster of 4)
#define HP 132          // padded row pitch for h in shared (bank-conflict-free)

// Device scratch (no cudaMalloc allowed)
__device__ float g_AL[BB * SS * KK];      // all_learning
__device__ float g_PRE2[BB * TT * KK];    // learning_pre@W2a + it@W2b + learning@W2c + b2
__device__ float g_PRE3[BB * TT * KK];    // same with W3
__device__ float g_PRE4[BB * TT * KK];    // it@W4c + b4
__device__ float g_PRE5[BB * TT * KK];    // e_next@W5a + b5

__device__ __forceinline__ float sigf(float x) { return 1.f / (1.f + __expf(-x)); }

// ---------------------------------------------------------------------------
// K1: all_learning[b,s,:] = [e_emb, at_emb, a*ones(50)] @ W1 + b1
// grid = B*S blocks, 128 threads
// ---------------------------------------------------------------------------
__global__ void k_allearn(const int* __restrict__ e_data, const int* __restrict__ at_data,
                          const float* __restrict__ a_data,
                          const float* __restrict__ e_E, const float* __restrict__ at_E,
                          const float* __restrict__ W1, const float* __restrict__ b1)
{
    int bs = blockIdx.x;
    int tid = threadIdx.x;
    __shared__ float se[128], sat[128];
    int e = e_data[bs];
    int at = at_data[bs];
    float a = a_data[bs];
    se[tid] = e_E[e * 128 + tid];
    sat[tid] = at_E[at * 128 + tid];
    __syncthreads();
    float acc = b1[tid];
#pragma unroll 8
    for (int i = 0; i < 128; i++) acc = fmaf(se[i], W1[i * 128 + tid], acc);
#pragma unroll 8
    for (int i = 0; i < 128; i++) acc = fmaf(sat[i], W1[(128 + i) * 128 + tid], acc);
    float cs = 0.f;
#pragma unroll 10
    for (int i = 0; i < 50; i++) cs += W1[(256 + i) * 128 + tid];
    acc = fmaf(a, cs, acc);
    g_AL[bs * 128 + tid] = acc;
}

// ---------------------------------------------------------------------------
// K2: per-(b,t) precomputables (carry-independent parts of the scan)
// grid = B*T blocks, 128 threads
// ---------------------------------------------------------------------------
__global__ void k_pre(const int* __restrict__ e_data, const int* __restrict__ it_data,
                      const float* __restrict__ it_E, const float* __restrict__ e_E,
                      const float* __restrict__ W2, const float* __restrict__ b2,
                      const float* __restrict__ W3, const float* __restrict__ b3,
                      const float* __restrict__ W4, const float* __restrict__ b4,
                      const float* __restrict__ W5, const float* __restrict__ b5)
{
    int blk = blockIdx.x;
    int b = blk / TT;
    int t = blk % TT;
    int tid = threadIdx.x;
    __shared__ float salp[128], sal[128], sit[128], se2[128];
    salp[tid] = (t > 0) ? g_AL[(b * SS + t - 1) * 128 + tid] : 0.f;
    sal[tid] = g_AL[(b * SS + t) * 128 + tid];
    int itv = it_data[b * SS + t];
    sit[tid] = it_E[itv * 128 + tid];
    int e2 = e_data[b * SS + t + 1];
    se2[tid] = e_E[e2 * 128 + tid];
    __syncthreads();
    float p2 = b2[tid], p3 = b3[tid], p4 = b4[tid], p5 = b5[tid];
#pragma unroll 4
    for (int i = 0; i < 128; i++) {
        float x = salp[i];
        p2 = fmaf(x, W2[i * 128 + tid], p2);
        p3 = fmaf(x, W3[i * 128 + tid], p3);
    }
#pragma unroll 4
    for (int i = 0; i < 128; i++) {
        float x = sit[i];
        p2 = fmaf(x, W2[(128 + i) * 128 + tid], p2);
        p3 = fmaf(x, W3[(128 + i) * 128 + tid], p3);
        p4 = fmaf(x, W4[(256 + i) * 128 + tid], p4);
    }
#pragma unroll 4
    for (int i = 0; i < 128; i++) {
        float x = sal[i];
        p2 = fmaf(x, W2[(256 + i) * 128 + tid], p2);
        p3 = fmaf(x, W3[(256 + i) * 128 + tid], p3);
    }
#pragma unroll 4
    for (int i = 0; i < 128; i++) p5 = fmaf(se2[i], W5[i * 128 + tid], p5);
    int o = (b * TT + t) * 128 + tid;
    g_PRE2[o] = p2;
    g_PRE3[o] = p3;
    g_PRE4[o] = p4;
    g_PRE5[o] = p5;
}

// ---------------------------------------------------------------------------
// K3: the sequential scan. 32 clusters x 4 CTAs; CTA rank r owns concepts
// [r*64, r*64+64). h slice + W4a + weight column slices resident in SMEM.
// Packed fp32x2 FMA for the dominant [64,128]@[128,128] per-step GEMM.
// ---------------------------------------------------------------------------
__global__ void __cluster_dims__(4, 1, 1) __launch_bounds__(256, 1)
k_scan(const int* __restrict__ e_data, const float* __restrict__ q_matrix,
       const float* __restrict__ h0,
       const float* __restrict__ W2, const float* __restrict__ W3,
       const float* __restrict__ W4, const float* __restrict__ W5,
       float* __restrict__ out)
{
    extern __shared__ float sm[];
    float* sh_w4a = sm;                  // 16384  (full W4a, [128][128])
    float* sh_h   = sh_w4a + 16384;      // 8448   (h slice [64][HP])
    float* sh_w2d = sh_h + 8448;         // 4096   ([128][32] col slice)
    float* sh_w3d = sh_w2d + 4096;       // 4096
    float* sh_w4b = sh_w3d + 4096;       // 4096   ([32][128] row slice)
    float* sh_w5b = sh_w4b + 4096;       // 4096   ([128][32] col slice)
    float* sh_pt  = sh_w5b + 4096;       // 2048   (partial h_tilde tiles [16][128])
    float* comm_pv = sh_pt + 2048;       // 128    (DSMEM: partial v)
    float* comm_ht = comm_pv + 128;      // 128    (DSMEM: partial h_tilde)
    float* comm_lg = comm_ht + 128;      // 32     (DSMEM: LG slice)
    float* sh_htld = comm_lg + 32;       // 128    (full h_tilde, replicated)
    float* sh_LG   = sh_htld + 128;      // 128    (full LG)
    float* sh_v    = sh_LG + 128;        // 128    (full v)
    float* sh_qe   = sh_v + 128;         // 64
    float* sh_qn   = sh_qe + 64;         // 64
    float* sh_lg   = sh_qn + 64;         // 32
    float* sh_gl   = sh_lg + 32;         // 32

    const int tid = threadIdx.x;
    const int b = blockIdx.x >> 2;
    const int rank = blockIdx.x & 3;
    const int c0 = rank * CS;
    cg::cluster_group cl = cg::this_cluster();

    // ---- load weights into shared ----
    for (int x = tid; x < 4096; x += 256)
        ((float4*)sh_w4a)[x] = ((const float4*)W4)[x];               // W4 rows 0..127
    for (int x = tid; x < 1024; x += 256)
        ((float4*)sh_w4b)[x] = ((const float4*)(W4 + 16384 + rank * 4096))[x];  // W4b row slice
    for (int x = tid; x < 4096; x += 256) {
        int i = x >> 5, j = x & 31;
        sh_w2d[x] = W2[(384 + i) * 128 + rank * 32 + j];
        sh_w3d[x] = W3[(384 + i) * 128 + rank * 32 + j];
        sh_w5b[x] = W5[(128 + i) * 128 + rank * 32 + j];
    }
    // ---- h init (broadcast h0) ----
    for (int x = tid; x < 8192; x += 256) {
        int c = x >> 7, k = x & 127;
        sh_h[c * HP + k] = h0[(c0 + c) * 128 + k];
    }
    // ---- initial h_tilde: q_all[:,0] . h0 ----
    int e0 = e_data[b * SS];
    if (tid < 64) sh_qe[tid] = q_matrix[e0 * 256 + c0 + tid];
    __syncthreads();
    if (tid < 128) {
        float s = 0.f;
#pragma unroll 8
        for (int c = 0; c < CS; c++) s = fmaf(sh_qe[c], sh_h[c * HP + tid], s);
        comm_ht[tid] = s;
    }
    cl.sync();
    float* peer_ht[4];
    float* peer_pv[4];
    float* peer_lg[4];
#pragma unroll
    for (int r = 0; r < 4; r++) {
        peer_ht[r] = cl.map_shared_rank(comm_ht, r);
        peer_pv[r] = cl.map_shared_rank(comm_pv, r);
        peer_lg[r] = cl.map_shared_rank(comm_lg, r);
    }
    if (tid < 128)
        sh_htld[tid] = peer_ht[0][tid] + peer_ht[1][tid] + peer_ht[2][tid] + peer_ht[3][tid];
    __syncthreads();

    const int rg = tid >> 4;
    const int cgid = tid & 15;
    const int row0 = rg * 4;
    const int col0 = cgid * 8;

    for (int t = 0; t < TT; t++) {
        const int base = (b * TT + t) * 128;
        // q rows for this step
        int e = e_data[b * SS + t];
        int en = e_data[b * SS + t + 1];
        if (tid < 64)
            sh_qe[tid] = q_matrix[e * 256 + c0 + tid];
        else if (tid < 128)
            sh_qn[tid - 64] = q_matrix[en * 256 + c0 + (tid - 64)];

        // --- phase 1: lg / gamma_l raw GEMV partials (column slice) ---
        {
            int j = (tid & 127) >> 2;
            int qtr = tid & 3;
            const float* Wd = (tid < 128) ? sh_w2d : sh_w3d;
            float s = 0.f;
            int i0 = qtr * 32;
#pragma unroll 8
            for (int i = i0; i < i0 + 32; i++) s = fmaf(sh_htld[i], Wd[i * 32 + j], s);
            s += __shfl_down_sync(0xffffffffu, s, 2);
            s += __shfl_down_sync(0xffffffffu, s, 1);
            if (qtr == 0) {
                if (tid < 128) sh_lg[j] = g_PRE2[base + rank * 32 + j] + s;
                else           sh_gl[j] = g_PRE3[base + rank * 32 + j] + s;
            }
        }
        __syncthreads();
        if (tid < 32)
            comm_lg[tid] = sigf(sh_gl[tid]) * (tanhf(sh_lg[tid]) + 1.f) * 0.5f;
        // --- y for previous step (uses current h_tilde = h_tilde_new of t-1) ---
        if (tid >= 128 && t > 0) {
            int tid2 = tid - 128;
            int j = tid2 >> 2, qtr = tid2 & 3;
            float s = 0.f;
            int i0 = qtr * 32;
#pragma unroll 8
            for (int i = i0; i < i0 + 32; i++) s = fmaf(sh_htld[i], sh_w5b[i * 32 + j], s);
            s += __shfl_down_sync(0xffffffffu, s, 2);
            s += __shfl_down_sync(0xffffffffu, s, 1);
            float val = 0.f;
            if (qtr == 0)
                val = sigf(g_PRE5[(b * TT + t - 1) * 128 + rank * 32 + j] + s);
#pragma unroll
            for (int o = 16; o > 0; o >>= 1) val += __shfl_down_sync(0xffffffffu, val, o);
            if ((tid & 31) == 0) atomicAdd(&out[b * SS + t], val * (1.f / 128.f));
        }
        __syncthreads();
        // --- partial v: LG_slice @ W4b_rows (full k) ---
        if (tid < 128) {
            float s = 0.f;
#pragma unroll 8
            for (int j = 0; j < 32; j++) s = fmaf(comm_lg[j], sh_w4b[j * 128 + tid], s);
            comm_pv[tid] = s;
        }
        cl.sync();  // #1: publish LG slices + partial v
        if (tid < 128) {
            float s = g_PRE4[base + tid];
            s += peer_pv[0][tid] + peer_pv[1][tid] + peer_pv[2][tid] + peer_pv[3][tid];
            sh_v[tid] = s;
            sh_LG[tid] = peer_lg[tid >> 5][tid & 31];
        }
        __syncthreads();

        // --- big GEMM dot phase: acc[r][c pair] = h_row . W4a_col (f32x2 packed) ---
        unsigned long long acc[4][4];
#pragma unroll
        for (int r = 0; r < 4; r++)
#pragma unroll
            for (int c = 0; c < 4; c++) acc[r][c] = 0ull;
#pragma unroll 4
        for (int i = 0; i < 128; i++) {
            unsigned long long hp[4];
#pragma unroll
            for (int r = 0; r < 4; r++) {
                unsigned hv = __float_as_uint(sh_h[(row0 + r) * HP + i]);
                asm("mov.b64 %0, {%1, %1};" : "=l"(hp[r]) : "r"(hv));
            }
            const ulonglong2* wp = (const ulonglong2*)(sh_w4a + i * 128 + col0);
            ulonglong2 w0 = wp[0];
            ulonglong2 w1 = wp[1];
#pragma unroll
            for (int r = 0; r < 4; r++) {
                asm("fma.rn.f32x2 %0, %1, %2, %0;" : "+l"(acc[r][0]) : "l"(hp[r]), "l"(w0.x));
                asm("fma.rn.f32x2 %0, %1, %2, %0;" : "+l"(acc[r][1]) : "l"(hp[r]), "l"(w0.y));
                asm("fma.rn.f32x2 %0, %1, %2, %0;" : "+l"(acc[r][2]) : "l"(hp[r]), "l"(w1.x));
                asm("fma.rn.f32x2 %0, %1, %2, %0;" : "+l"(acc[r][3]) : "l"(hp[r]), "l"(w1.y));
            }
        }
        __syncthreads();
        // --- update phase: gamma_f, h_new, partial h_tilde tile ---
        {
            float pt[8];
#pragma unroll
            for (int c = 0; c < 8; c++) pt[c] = 0.f;
#pragma unroll
            for (int r = 0; r < 4; r++) {
                int c = row0 + r;
                float qe = sh_qe[c];
                float qn = sh_qn[c];
#pragma unroll
                for (int p = 0; p < 4; p++) {
                    unsigned long long a2 = acc[r][p];
                    float d0 = __uint_as_float((unsigned)a2);
                    float d1 = __uint_as_float((unsigned)(a2 >> 32));
                    int k0 = col0 + 2 * p;
                    float g0 = sigf(d0 + sh_v[k0]);
                    float g1 = sigf(d1 + sh_v[k0 + 1]);
                    float h0v = sh_h[c * HP + k0];
                    float h1v = sh_h[c * HP + k0 + 1];
                    float hn0 = fmaf(qe, sh_LG[k0], g0 * h0v);
                    float hn1 = fmaf(qe, sh_LG[k0 + 1], g1 * h1v);
                    sh_h[c * HP + k0] = hn0;
                    sh_h[c * HP + k0 + 1] = hn1;
                    pt[2 * p]     = fmaf(qn, hn0, pt[2 * p]);
                    pt[2 * p + 1] = fmaf(qn, hn1, pt[2 * p + 1]);
                }
            }
#pragma unroll
            for (int c = 0; c < 8; c++) sh_pt[rg * 128 + col0 + c] = pt[c];
        }
        __syncthreads();
        if (tid < 128) {
            float s = 0.f;
#pragma unroll
            for (int r = 0; r < 16; r++) s += sh_pt[r * 128 + tid];
            comm_ht[tid] = s;
        }
        cl.sync();  // #2: publish partial h_tilde
        if (tid < 128)
            sh_htld[tid] = peer_ht[0][tid] + peer_ht[1][tid] + peer_ht[2][tid] + peer_ht[3][tid];
        __syncthreads();
    }

    // --- final y (t = T-1) -> pred[:, S-1] ---
    if (tid >= 128) {
        int tid2 = tid - 128;
        int j = tid2 >> 2, qtr = tid2 & 3;
        float s = 0.f;
        int i0 = qtr * 32;
#pragma unroll 8
        for (int i = i0; i < i0 + 32; i++) s = fmaf(sh_htld[i], sh_w5b[i * 32 + j], s);
        s += __shfl_down_sync(0xffffffffu, s, 2);
        s += __shfl_down_sync(0xffffffffu, s, 1);
        float val = 0.f;
        if (qtr == 0)
            val = sigf(g_PRE5[(b * TT + TT - 1) * 128 + rank * 32 + j] + s);
#pragma unroll
        for (int o = 16; o > 0; o >>= 1) val += __shfl_down_sync(0xffffffffu, val, o);
        if ((tid & 31) == 0) atomicAdd(&out[b * SS + SS - 1], val * (1.f / 128.f));
    }
}

static const unsigned SCAN_SMEM = 180224;  // 44128 floats actually used

extern "C" void kernel_launch(void* const* d_in, const int* in_sizes, int n_in,
                              void* d_out, int out_size)
{
    const int* e_data = (const int*)d_in[0];
    const int* at_data = (const int*)d_in[1];
    const int* it_data = (const int*)d_in[2];
    const float* a_data = (const float*)d_in[3];
    const float* q_matrix = (const float*)d_in[4];
    const float* e_E = (const float*)d_in[5];
    const float* at_E = (const float*)d_in[6];
    const float* it_E = (const float*)d_in[7];
    const float* W1 = (const float*)d_in[8];
    const float* b1 = (const float*)d_in[9];
    const float* W2 = (const float*)d_in[10];
    const float* b2 = (const float*)d_in[11];
    const float* W3 = (const float*)d_in[12];
    const float* b3 = (const float*)d_in[13];
    const float* W4 = (const float*)d_in[14];
    const float* b4 = (const float*)d_in[15];
    const float* W5 = (const float*)d_in[16];
    const float* b5 = (const float*)d_in[17];
    const float* h0 = (const float*)d_in[18];
    float* out = (float*)d_out;

    cudaFuncSetAttribute(k_scan, cudaFuncAttributeMaxDynamicSharedMemorySize, SCAN_SMEM);

    cudaMemsetAsync(out, 0, BB * SS * sizeof(float));
    k_allearn<<<BB * SS, 128>>>(e_data, at_data, a_data, e_E, at_E, W1, b1);
    k_pre<<<BB * TT, 128>>>(e_data, it_data, it_E, e_E, W2, b2, W3, b3, W4, b4, W5, b5);
    k_scan<<<BB * 4, 256, SCAN_SMEM>>>(e_data, q_matrix, h0, W2, W3, W4, W5, out);
}

// round 7
// speedup vs baseline: 2.3729x; 2.3729x over previous
#include <cuda_runtime.h>
#include <cuda_bf16.h>
#include <cstdint>
#include <cooperative_groups.h>

namespace cg = cooperative_groups;

#define BB 32
#define SS 128
#define TT 127
#define CS 64           // concepts per CTA (cluster of 4)
#define PB 272          // hbf byte pitch per concept row (136 bf16, destaggered)

// ---------------- device scratch ----------------
__device__ float g_AL[BB * SS * 128];
__device__ float g_PRE2[BB * TT * 128];
__device__ float g_PRE3[BB * TT * 128];
__device__ float g_PRE4[BB * TT * 128];
__device__ float g_PRE5[BB * TT * 128];

// fast tanh/sigmoid (MUFU.TANH, sm_75+)
__device__ __forceinline__ float tanh_ap(float x) {
    float y; asm("tanh.approx.f32 %0, %1;" : "=f"(y) : "f"(x)); return y;
}
__device__ __forceinline__ float sigf(float x) { return fmaf(0.5f, tanh_ap(0.5f * x), 0.5f); }

// pack two fp32 -> bf16x2 (lo in bits 0..15)
__device__ __forceinline__ uint32_t packbf(float lo, float hi) {
    uint32_t r; asm("cvt.rn.bf16x2.f32 %0, %1, %2;" : "=r"(r) : "f"(hi), "f"(lo)); return r;
}

// m16n8k16 row.col f32.bf16.bf16.f32, D accumulates in place
__device__ __forceinline__ void mma_bf16(float* d, const uint32_t* a, const uint32_t* b) {
    asm volatile("mma.sync.aligned.m16n8k16.row.col.f32.bf16.bf16.f32 "
                 "{%0,%1,%2,%3}, {%4,%5,%6,%7}, {%8,%9}, {%0,%1,%2,%3};"
                 : "+f"(d[0]), "+f"(d[1]), "+f"(d[2]), "+f"(d[3])
                 : "r"(a[0]), "r"(a[1]), "r"(a[2]), "r"(a[3]), "r"(b[0]), "r"(b[1]));
}

// ---------------------------------------------------------------------------
// K1: all_learning
// ---------------------------------------------------------------------------
__global__ void k_allearn(const int* __restrict__ e_data, const int* __restrict__ at_data,
                          const float* __restrict__ a_data,
                          const float* __restrict__ e_E, const float* __restrict__ at_E,
                          const float* __restrict__ W1, const float* __restrict__ b1)
{
    int bs = blockIdx.x;
    int tid = threadIdx.x;
    __shared__ float se[128], sat[128];
    int e = e_data[bs];
    int at = at_data[bs];
    float a = a_data[bs];
    se[tid] = e_E[e * 128 + tid];
    sat[tid] = at_E[at * 128 + tid];
    __syncthreads();
    float acc = b1[tid];
#pragma unroll 8
    for (int i = 0; i < 128; i++) acc = fmaf(se[i], W1[i * 128 + tid], acc);
#pragma unroll 8
    for (int i = 0; i < 128; i++) acc = fmaf(sat[i], W1[(128 + i) * 128 + tid], acc);
    float cs = 0.f;
#pragma unroll 10
    for (int i = 0; i < 50; i++) cs += W1[(256 + i) * 128 + tid];
    acc = fmaf(a, cs, acc);
    g_AL[bs * 128 + tid] = acc;
}

// ---------------------------------------------------------------------------
// K2: carry-independent precomputables
// ---------------------------------------------------------------------------
__global__ void k_pre(const int* __restrict__ e_data, const int* __restrict__ it_data,
                      const float* __restrict__ it_E, const float* __restrict__ e_E,
                      const float* __restrict__ W2, const float* __restrict__ b2,
                      const float* __restrict__ W3, const float* __restrict__ b3,
                      const float* __restrict__ W4, const float* __restrict__ b4,
                      const float* __restrict__ W5, const float* __restrict__ b5)
{
    int blk = blockIdx.x;
    int b = blk / TT;
    int t = blk % TT;
    int tid = threadIdx.x;
    __shared__ float salp[128], sal[128], sit[128], se2[128];
    salp[tid] = (t > 0) ? g_AL[(b * SS + t - 1) * 128 + tid] : 0.f;
    sal[tid] = g_AL[(b * SS + t) * 128 + tid];
    int itv = it_data[b * SS + t];
    sit[tid] = it_E[itv * 128 + tid];
    int e2 = e_data[b * SS + t + 1];
    se2[tid] = e_E[e2 * 128 + tid];
    __syncthreads();
    float p2 = b2[tid], p3 = b3[tid], p4 = b4[tid], p5 = b5[tid];
#pragma unroll 4
    for (int i = 0; i < 128; i++) {
        float x = salp[i];
        p2 = fmaf(x, W2[i * 128 + tid], p2);
        p3 = fmaf(x, W3[i * 128 + tid], p3);
    }
#pragma unroll 4
    for (int i = 0; i < 128; i++) {
        float x = sit[i];
        p2 = fmaf(x, W2[(128 + i) * 128 + tid], p2);
        p3 = fmaf(x, W3[(128 + i) * 128 + tid], p3);
        p4 = fmaf(x, W4[(256 + i) * 128 + tid], p4);
    }
#pragma unroll 4
    for (int i = 0; i < 128; i++) {
        float x = sal[i];
        p2 = fmaf(x, W2[(256 + i) * 128 + tid], p2);
        p3 = fmaf(x, W3[(256 + i) * 128 + tid], p3);
    }
#pragma unroll 4
    for (int i = 0; i < 128; i++) p5 = fmaf(se2[i], W5[i * 128 + tid], p5);
    int o = (b * TT + t) * 128 + tid;
    g_PRE2[o] = p2;
    g_PRE3[o] = p3;
    g_PRE4[o] = p4;
    g_PRE5[o] = p5;
}

// ---------------------------------------------------------------------------
// K3: scan. 32 clusters x 4 CTAs (rank owns 64 concepts).
// D[c,j] = h[c,k] @ W4a[k,j] via mma.sync bf16; W4a B-frags static in regs,
// h master fp32 in D-frag registers, bf16 shadow in SMEM for the A operand.
// Warp (wc = wid&3, jh = wid>>2): c-tile [16*wc,+16), j-half [64*jh,+64).
// ---------------------------------------------------------------------------
#define O_HBF   0         // 17408: bf16 h [64][PB]
#define O_W5B   17408     // 65536: W5 rows 128..255 [128][128] f32
#define O_W2D   82944     // 16384: [128][32] col slice
#define O_W3D   99328     // 16384
#define O_W4B   115712    // 16384: [32][128] row slice
#define O_PTB   132096    // 2048:  [4 wc][128 j] partial h_tilde
#define O_PV    134144    // 512  comm: partial v
#define O_HT    134656    // 512  comm: partial h_tilde (cluster)
#define O_CLG   135168    // 128  comm: LG slice
#define O_HTLD  135296    // 512
#define O_SLG   135808    // 512
#define O_SV    136320    // 512
#define O_QE    136832    // 256
#define O_QN    137088    // 256
#define O_LGR   137344    // 128
#define O_GLR   137472    // 128
#define O_Y4    137600    // 128
#define SMEM_END 137728
static const unsigned SCAN_SMEM = SMEM_END + 1024;

__global__ void __cluster_dims__(4, 1, 1) __launch_bounds__(256, 1)
k_scan(const int* __restrict__ e_data, const float* __restrict__ q_matrix,
       const float* __restrict__ h0,
       const float* __restrict__ W4, const float* __restrict__ W5,
       const float* __restrict__ W2, const float* __restrict__ W3,
       float* __restrict__ out)
{
    extern __shared__ char smraw[];
    char* smb = (char*)(((uintptr_t)smraw + 1023) & ~(uintptr_t)1023);
    float* w5b   = (float*)(smb + O_W5B);
    float* w2d   = (float*)(smb + O_W2D);
    float* w3d   = (float*)(smb + O_W3D);
    float* w4b   = (float*)(smb + O_W4B);
    float* ptb   = (float*)(smb + O_PTB);
    float* comm_pv = (float*)(smb + O_PV);
    float* comm_ht = (float*)(smb + O_HT);
    float* comm_lg = (float*)(smb + O_CLG);
    float* htld  = (float*)(smb + O_HTLD);
    float* sLG   = (float*)(smb + O_SLG);
    float* sv    = (float*)(smb + O_SV);
    float* qe    = (float*)(smb + O_QE);
    float* qn    = (float*)(smb + O_QN);
    float* slg   = (float*)(smb + O_LGR);
    float* sgl   = (float*)(smb + O_GLR);
    float* y4    = (float*)(smb + O_Y4);

    const int tid  = threadIdx.x;
    const int wid  = tid >> 5;
    const int lane = tid & 31;
    const int g    = lane >> 2;       // 0..7
    const int t4   = lane & 3;        // 0..3
    const int wc   = wid & 3;         // c-tile
    const int jh   = wid >> 2;        // j-half
    const int b    = blockIdx.x >> 2;
    const int rank = blockIdx.x & 3;
    const int c0   = rank * CS;
    const int cl_lo = wc * 16 + g;    // local c of d0/d1
    const int cl_hi = cl_lo + 8;      // local c of d2/d3
    cg::cluster_group cl = cg::this_cluster();

    // ---- weights into shared ----
    for (int x = tid; x < 16384; x += 256)
        w5b[x] = W5[(128 + (x >> 7)) * 128 + (x & 127)];
    for (int x = tid; x < 4096; x += 256) {
        int i = x >> 5, j = x & 31;
        w2d[x] = W2[(384 + i) * 128 + rank * 32 + j];
        w3d[x] = W3[(384 + i) * 128 + rank * 32 + j];
    }
    for (int x = tid; x < 1024; x += 256)
        ((float4*)w4b)[x] = ((const float4*)(W4 + 16384 + rank * 4096))[x];

    // ---- static B fragments: W4a^T bf16 (col-major [16k x 8n] per tile) ----
    uint32_t bst[8][8][2];
#pragma unroll
    for (int nt = 0; nt < 8; nt++) {
        int j = jh * 64 + nt * 8 + g;
#pragma unroll
        for (int ks = 0; ks < 8; ks++) {
            int k0 = ks * 16 + 2 * t4;
            bst[nt][ks][0] = packbf(W4[k0 * 128 + j],        W4[(k0 + 1) * 128 + j]);
            bst[nt][ks][1] = packbf(W4[(k0 + 8) * 128 + j],  W4[(k0 + 9) * 128 + j]);
        }
    }

    // ---- h master (fp32 regs, D-frag layout) + bf16 shadow in SMEM ----
    float hreg[8][4];
#pragma unroll
    for (int nt = 0; nt < 8; nt++) {
        int j0 = jh * 64 + nt * 8 + 2 * t4;
        hreg[nt][0] = h0[(c0 + cl_lo) * 128 + j0];
        hreg[nt][1] = h0[(c0 + cl_lo) * 128 + j0 + 1];
        hreg[nt][2] = h0[(c0 + cl_hi) * 128 + j0];
        hreg[nt][3] = h0[(c0 + cl_hi) * 128 + j0 + 1];
        *(uint32_t*)(smb + O_HBF + cl_lo * PB + j0 * 2) = packbf(hreg[nt][0], hreg[nt][1]);
        *(uint32_t*)(smb + O_HBF + cl_hi * PB + j0 * 2) = packbf(hreg[nt][2], hreg[nt][3]);
    }

    // ---- initial h_tilde = q[e0] . h0 ----
    int e0 = e_data[b * SS];
    if (tid < 64) qn[tid] = q_matrix[e0 * 256 + c0 + tid];
    __syncthreads();
    {
        float qnl = qn[cl_lo], qnh = qn[cl_hi];
        float ptp[8][2];
#pragma unroll
        for (int nt = 0; nt < 8; nt++) {
            ptp[nt][0] = fmaf(qnl, hreg[nt][0], qnh * hreg[nt][2]);
            ptp[nt][1] = fmaf(qnl, hreg[nt][1], qnh * hreg[nt][3]);
        }
#pragma unroll
        for (int nt = 0; nt < 8; nt++)
#pragma unroll
            for (int o = 16; o >= 4; o >>= 1) {
                ptp[nt][0] += __shfl_down_sync(0xffffffffu, ptp[nt][0], o);
                ptp[nt][1] += __shfl_down_sync(0xffffffffu, ptp[nt][1], o);
            }
        if (lane < 4) {
#pragma unroll
            for (int nt = 0; nt < 8; nt++)
                *(float2*)(ptb + wc * 128 + jh * 64 + nt * 8 + 2 * lane) =
                    make_float2(ptp[nt][0], ptp[nt][1]);
        }
    }
    __syncthreads();
    if (tid < 128) comm_ht[tid] = ptb[tid] + ptb[128 + tid] + ptb[256 + tid] + ptb[384 + tid];
    cl.sync();
    float* peer_ht[4];
    float* peer_pv[4];
    float* peer_lg[4];
#pragma unroll
    for (int r = 0; r < 4; r++) {
        peer_ht[r] = cl.map_shared_rank(comm_ht, r);
        peer_pv[r] = cl.map_shared_rank(comm_pv, r);
        peer_lg[r] = cl.map_shared_rank(comm_lg, r);
    }
    if (tid < 128)
        htld[tid] = peer_ht[0][tid] + peer_ht[1][tid] + peer_ht[2][tid] + peer_ht[3][tid];
    __syncthreads();

    for (int t = 0; t < TT; t++) {
        const int base = (b * TT + t) * 128;
        int e = e_data[b * SS + t];
        int en = e_data[b * SS + t + 1];
        if (tid < 64)       qe[tid] = q_matrix[e * 256 + c0 + tid];
        else if (tid < 128) qn[tid - 64] = q_matrix[en * 256 + c0 + (tid - 64)];

        // ---- lg/gl slice GEMVs (htld part) ----
        {
            int j = (tid & 127) >> 2;
            int qtr = tid & 3;
            const float* Wd = (tid < 128) ? w2d : w3d;
            float s = 0.f;
            int i0 = qtr * 32;
#pragma unroll 8
            for (int i = i0; i < i0 + 32; i++) s = fmaf(htld[i], Wd[i * 32 + j], s);
            s += __shfl_down_sync(0xffffffffu, s, 2);
            s += __shfl_down_sync(0xffffffffu, s, 1);
            if (qtr == 0) {
                if (tid < 128) slg[j] = g_PRE2[base + rank * 32 + j] + s;
                else           sgl[j] = g_PRE3[base + rank * 32 + j] + s;
            }
        }
        __syncthreads();
        if (tid < 32)
            comm_lg[tid] = sigf(sgl[tid]) * (tanh_ap(slg[tid]) + 1.f) * 0.5f;
        __syncthreads();

        if (tid < 128) {
            // partial v = LG_slice @ W4b_slice
            float s = 0.f;
#pragma unroll 8
            for (int j = 0; j < 32; j++) s = fmaf(comm_lg[j], w4b[j * 128 + tid], s);
            comm_pv[tid] = s;
        } else {
            // y(t-1), all 128 cols, warps 4-7
            int j = tid - 128;
            float s = 0.f;
#pragma unroll 4
            for (int i = 0; i < 128; i++) s = fmaf(htld[i], w5b[i * 128 + j], s);
            float val = (t > 0) ? sigf(g_PRE5[(b * TT + t - 1) * 128 + j] + s) : 0.f;
#pragma unroll
            for (int o = 16; o > 0; o >>= 1) val += __shfl_down_sync(0xffffffffu, val, o);
            if (lane == 0) y4[wid - 4] = val;
        }

        // ---- GEMM: D[c,j] (register), A = h bf16 shadow, B = static frags ----
        float dfr[8][4];
#pragma unroll
        for (int nt = 0; nt < 8; nt++) {
            dfr[nt][0] = 0.f; dfr[nt][1] = 0.f; dfr[nt][2] = 0.f; dfr[nt][3] = 0.f;
        }
#pragma unroll
        for (int ks = 0; ks < 8; ks++) {
            uint32_t a[4];
            a[0] = *(const uint32_t*)(smb + O_HBF + cl_lo * PB + ks * 32 + t4 * 4);
            a[1] = *(const uint32_t*)(smb + O_HBF + cl_hi * PB + ks * 32 + t4 * 4);
            a[2] = *(const uint32_t*)(smb + O_HBF + cl_lo * PB + ks * 32 + t4 * 4 + 16);
            a[3] = *(const uint32_t*)(smb + O_HBF + cl_hi * PB + ks * 32 + t4 * 4 + 16);
#pragma unroll
            for (int nt = 0; nt < 8; nt++) mma_bf16(dfr[nt], a, bst[nt][ks]);
        }

        cl.sync();  // #1: LG slices + partial v published; separates GEMM reads from h writes

        if (tid < 128) {
            float s = g_PRE4[base + tid];
            s += peer_pv[0][tid] + peer_pv[1][tid] + peer_pv[2][tid] + peer_pv[3][tid];
            sv[tid] = s;
            sLG[tid] = peer_lg[tid >> 5][tid & 31];
        }
        if (rank == 0 && tid == 0 && t > 0)
            out[b * SS + t] = (y4[0] + y4[1] + y4[2] + y4[3]) * (1.f / 128.f);
        __syncthreads();

        // ---- update (registers) ----
        {
            float qel = qe[cl_lo], qeh = qe[cl_hi];
            float qnl = qn[cl_lo], qnh = qn[cl_hi];
            float ptp[8][2];
#pragma unroll
            for (int nt = 0; nt < 8; nt++) {
                int j0 = jh * 64 + nt * 8 + 2 * t4;
                float2 v2 = *(const float2*)(sv + j0);
                float2 l2 = *(const float2*)(sLG + j0);
                float g0 = sigf(dfr[nt][0] + v2.x);
                float g1 = sigf(dfr[nt][1] + v2.y);
                float g2 = sigf(dfr[nt][2] + v2.x);
                float g3 = sigf(dfr[nt][3] + v2.y);
                float h0n = fmaf(qel, l2.x, g0 * hreg[nt][0]);
                float h1n = fmaf(qel, l2.y, g1 * hreg[nt][1]);
                float h2n = fmaf(qeh, l2.x, g2 * hreg[nt][2]);
                float h3n = fmaf(qeh, l2.y, g3 * hreg[nt][3]);
                hreg[nt][0] = h0n; hreg[nt][1] = h1n;
                hreg[nt][2] = h2n; hreg[nt][3] = h3n;
                *(uint32_t*)(smb + O_HBF + cl_lo * PB + j0 * 2) = packbf(h0n, h1n);
                *(uint32_t*)(smb + O_HBF + cl_hi * PB + j0 * 2) = packbf(h2n, h3n);
                ptp[nt][0] = fmaf(qnl, h0n, qnh * h2n);
                ptp[nt][1] = fmaf(qnl, h1n, qnh * h3n);
            }
#pragma unroll
            for (int nt = 0; nt < 8; nt++)
#pragma unroll
                for (int o = 16; o >= 4; o >>= 1) {
                    ptp[nt][0] += __shfl_down_sync(0xffffffffu, ptp[nt][0], o);
                    ptp[nt][1] += __shfl_down_sync(0xffffffffu, ptp[nt][1], o);
                }
            if (lane < 4) {
#pragma unroll
                for (int nt = 0; nt < 8; nt++)
                    *(float2*)(ptb + wc * 128 + jh * 64 + nt * 8 + 2 * lane) =
                        make_float2(ptp[nt][0], ptp[nt][1]);
            }
        }
        __syncthreads();
        if (tid < 128) comm_ht[tid] = ptb[tid] + ptb[128 + tid] + ptb[256 + tid] + ptb[384 + tid];
        cl.sync();  // #2: publish partial h_tilde
        if (tid < 128)
            htld[tid] = peer_ht[0][tid] + peer_ht[1][tid] + peer_ht[2][tid] + peer_ht[3][tid];
        __syncthreads();
    }

    // ---- final y (t = TT-1 -> pred[:, S-1]) ----
    if (tid >= 128) {
        int j = tid - 128;
        float s = 0.f;
#pragma unroll 4
        for (int i = 0; i < 128; i++) s = fmaf(htld[i], w5b[i * 128 + j], s);
        float val = sigf(g_PRE5[(b * TT + TT - 1) * 128 + j] + s);
#pragma unroll
        for (int o = 16; o > 0; o >>= 1) val += __shfl_down_sync(0xffffffffu, val, o);
        if (lane == 0) y4[wid - 4] = val;
    }
    __syncthreads();
    if (rank == 0 && tid == 0) {
        out[b * SS + SS - 1] = (y4[0] + y4[1] + y4[2] + y4[3]) * (1.f / 128.f);
        out[b * SS] = 0.f;
    }
}

extern "C" void kernel_launch(void* const* d_in, const int* in_sizes, int n_in,
                              void* d_out, int out_size)
{
    const int* e_data = (const int*)d_in[0];
    const int* at_data = (const int*)d_in[1];
    const int* it_data = (const int*)d_in[2];
    const float* a_data = (const float*)d_in[3];
    const float* q_matrix = (const float*)d_in[4];
    const float* e_E = (const float*)d_in[5];
    const float* at_E = (const float*)d_in[6];
    const float* it_E = (const float*)d_in[7];
    const float* W1 = (const float*)d_in[8];
    const float* b1 = (const float*)d_in[9];
    const float* W2 = (const float*)d_in[10];
    const float* b2 = (const float*)d_in[11];
    const float* W3 = (const float*)d_in[12];
    const float* b3 = (const float*)d_in[13];
    const float* W4 = (const float*)d_in[14];
    const float* b4 = (const float*)d_in[15];
    const float* W5 = (const float*)d_in[16];
    const float* b5 = (const float*)d_in[17];
    const float* h0 = (const float*)d_in[18];
    float* out = (float*)d_out;

    cudaFuncSetAttribute(k_scan, cudaFuncAttributeMaxDynamicSharedMemorySize, SCAN_SMEM);

    k_allearn<<<BB * SS, 128>>>(e_data, at_data, a_data, e_E, at_E, W1, b1);
    k_pre<<<BB * TT, 128>>>(e_data, it_data, it_E, e_E, W2, b2, W3, b3, W4, b4, W5, b5);
    k_scan<<<BB * 4, 256, SCAN_SMEM>>>(e_data, q_matrix, h0, W4, W5, W2, W3, out);
}

// round 8
// speedup vs baseline: 2.9026x; 1.2232x over previous
#include <cuda_runtime.h>
#include <cuda_bf16.h>
#include <cstdint>
#include <cooperative_groups.h>

namespace cg = cooperative_groups;

#define BB 32
#define SS 128
#define TT 127
#define CS 64

__device__ float g_AL[BB * SS * 128];
__device__ float g_PRE2[BB * TT * 128];
__device__ float g_PRE3[BB * TT * 128];
__device__ float g_PRE4[BB * TT * 128];
__device__ float g_PRE5[BB * TT * 128];

__device__ __forceinline__ float tanh_ap(float x) {
    float y; asm("tanh.approx.f32 %0, %1;" : "=f"(y) : "f"(x)); return y;
}
__device__ __forceinline__ float sigf(float x) { return fmaf(0.5f, tanh_ap(0.5f * x), 0.5f); }
__device__ __forceinline__ uint32_t packbf(float lo, float hi) {
    uint32_t r; asm("cvt.rn.bf16x2.f32 %0, %1, %2;" : "=r"(r) : "f"(hi), "f"(lo)); return r;
}
__device__ __forceinline__ void mma_bf16(float* d, uint32_t a0, uint32_t a1, uint32_t a2,
                                         uint32_t a3, uint32_t b0, uint32_t b1) {
    asm volatile("mma.sync.aligned.m16n8k16.row.col.f32.bf16.bf16.f32 "
                 "{%0,%1,%2,%3}, {%4,%5,%6,%7}, {%8,%9}, {%0,%1,%2,%3};"
                 : "+f"(d[0]), "+f"(d[1]), "+f"(d[2]), "+f"(d[3])
                 : "r"(a0), "r"(a1), "r"(a2), "r"(a3), "r"(b0), "r"(b1));
}
__device__ __forceinline__ int hsw(int k) { return k ^ ((k >> 5) << 3); }

// ---------------------------------------------------------------------------
// K1: all_learning, 32 rows per block, W1 streamed once per 32 rows
// ---------------------------------------------------------------------------
#define ATILE 32
__global__ void k_allearn(const int* __restrict__ e_data, const int* __restrict__ at_data,
                          const float* __restrict__ a_data,
                          const float* __restrict__ e_E, const float* __restrict__ at_E,
                          const float* __restrict__ W1, const float* __restrict__ b1)
{
    __shared__ float se_t[128 * 36], sat_t[128 * 36];
    __shared__ float av[ATILE];
    __shared__ int ev[ATILE], atv[ATILE];
    int blk = blockIdx.x, tid = threadIdx.x;
    if (tid < ATILE) {
        int bs = blk * ATILE + tid;
        ev[tid] = e_data[bs]; atv[tid] = at_data[bs]; av[tid] = a_data[bs];
    }
    __syncthreads();
    for (int x = tid; x < ATILE * 128; x += 128) {
        int r = x >> 7, k = x & 127;
        se_t[k * 36 + r] = e_E[ev[r] * 128 + k];
        sat_t[k * 36 + r] = at_E[atv[r] * 128 + k];
    }
    __syncthreads();
    float acc[ATILE];
#pragma unroll
    for (int r = 0; r < ATILE; r++) acc[r] = 0.f;
    float cs = 0.f;
#pragma unroll 5
    for (int i = 0; i < 50; i++) cs += W1[(256 + i) * 128 + tid];
#pragma unroll 2
    for (int k = 0; k < 128; k++) {
        float w = W1[k * 128 + tid];
        const float4* xp = (const float4*)&se_t[k * 36];
#pragma unroll
        for (int r4 = 0; r4 < 8; r4++) {
            float4 x4 = xp[r4];
            acc[r4 * 4 + 0] = fmaf(x4.x, w, acc[r4 * 4 + 0]);
            acc[r4 * 4 + 1] = fmaf(x4.y, w, acc[r4 * 4 + 1]);
            acc[r4 * 4 + 2] = fmaf(x4.z, w, acc[r4 * 4 + 2]);
            acc[r4 * 4 + 3] = fmaf(x4.w, w, acc[r4 * 4 + 3]);
        }
    }
#pragma unroll 2
    for (int k = 0; k < 128; k++) {
        float w = W1[(128 + k) * 128 + tid];
        const float4* xp = (const float4*)&sat_t[k * 36];
#pragma unroll
        for (int r4 = 0; r4 < 8; r4++) {
            float4 x4 = xp[r4];
            acc[r4 * 4 + 0] = fmaf(x4.x, w, acc[r4 * 4 + 0]);
            acc[r4 * 4 + 1] = fmaf(x4.y, w, acc[r4 * 4 + 1]);
            acc[r4 * 4 + 2] = fmaf(x4.z, w, acc[r4 * 4 + 2]);
            acc[r4 * 4 + 3] = fmaf(x4.w, w, acc[r4 * 4 + 3]);
        }
    }
    float bb = b1[tid];
#pragma unroll
    for (int r = 0; r < ATILE; r++)
        g_AL[(blk * ATILE + r) * 128 + tid] = acc[r] + fmaf(av[r], cs, bb);
}

// ---------------------------------------------------------------------------
// K2: precomputables, 8 (b,t) rows per block
// ---------------------------------------------------------------------------
#define PTILE 8
__global__ void k_pre(const int* __restrict__ e_data, const int* __restrict__ it_data,
                      const float* __restrict__ it_E, const float* __restrict__ e_E,
                      const float* __restrict__ W2, const float* __restrict__ b2,
                      const float* __restrict__ W3, const float* __restrict__ b3,
                      const float* __restrict__ W4, const float* __restrict__ b4,
                      const float* __restrict__ W5, const float* __restrict__ b5)
{
    __shared__ float xa[128 * PTILE], xb[128 * PTILE], xc[128 * PTILE], xd[128 * PTILE];
    __shared__ int itv[PTILE], env[PTILE];
    int blk = blockIdx.x, tid = threadIdx.x;
    int row0 = blk * PTILE;
    if (tid < PTILE) {
        int row = row0 + tid, b = row / TT, t = row % TT;
        itv[tid] = it_data[b * SS + t];
        env[tid] = e_data[b * SS + t + 1];
    }
    __syncthreads();
    for (int x = tid; x < 128 * PTILE; x += 128) {
        int r = x >> 7, k = x & 127;
        int row = row0 + r, b = row / TT, t = row % TT;
        xa[k * 8 + r] = (t > 0) ? g_AL[(b * SS + t - 1) * 128 + k] : 0.f;
        xc[k * 8 + r] = g_AL[(b * SS + t) * 128 + k];
        xb[k * 8 + r] = it_E[itv[r] * 128 + k];
        xd[k * 8 + r] = e_E[env[r] * 128 + k];
    }
    __syncthreads();
    float p2[8], p3[8], p4[8], p5[8];
#pragma unroll
    for (int r = 0; r < 8; r++) { p2[r] = 0.f; p3[r] = 0.f; p4[r] = 0.f; p5[r] = 0.f; }
#pragma unroll 2
    for (int k = 0; k < 128; k++) {
        float w2 = W2[k * 128 + tid], w3 = W3[k * 128 + tid];
        float4 x0 = *(const float4*)&xa[k * 8], x1 = *(const float4*)&xa[k * 8 + 4];
        float xs[8] = {x0.x, x0.y, x0.z, x0.w, x1.x, x1.y, x1.z, x1.w};
#pragma unroll
        for (int r = 0; r < 8; r++) { p2[r] = fmaf(xs[r], w2, p2[r]); p3[r] = fmaf(xs[r], w3, p3[r]); }
    }
#pragma unroll 2
    for (int k = 0; k < 128; k++) {
        float w2 = W2[(128 + k) * 128 + tid], w3 = W3[(128 + k) * 128 + tid];
        float w4 = W4[(256 + k) * 128 + tid];
        float4 x0 = *(const float4*)&xb[k * 8], x1 = *(const float4*)&xb[k * 8 + 4];
        float xs[8] = {x0.x, x0.y, x0.z, x0.w, x1.x, x1.y, x1.z, x1.w};
#pragma unroll
        for (int r = 0; r < 8; r++) {
            p2[r] = fmaf(xs[r], w2, p2[r]); p3[r] = fmaf(xs[r], w3, p3[r]);
            p4[r] = fmaf(xs[r], w4, p4[r]);
        }
    }
#pragma unroll 2
    for (int k = 0; k < 128; k++) {
        float w2 = W2[(256 + k) * 128 + tid], w3 = W3[(256 + k) * 128 + tid];
        float4 x0 = *(const float4*)&xc[k * 8], x1 = *(const float4*)&xc[k * 8 + 4];
        float xs[8] = {x0.x, x0.y, x0.z, x0.w, x1.x, x1.y, x1.z, x1.w};
#pragma unroll
        for (int r = 0; r < 8; r++) { p2[r] = fmaf(xs[r], w2, p2[r]); p3[r] = fmaf(xs[r], w3, p3[r]); }
    }
#pragma unroll 2
    for (int k = 0; k < 128; k++) {
        float w5 = W5[k * 128 + tid];
        float4 x0 = *(const float4*)&xd[k * 8], x1 = *(const float4*)&xd[k * 8 + 4];
        float xs[8] = {x0.x, x0.y, x0.z, x0.w, x1.x, x1.y, x1.z, x1.w};
#pragma unroll
        for (int r = 0; r < 8; r++) p5[r] = fmaf(xs[r], w5, p5[r]);
    }
    float c2 = b2[tid], c3 = b3[tid], c4 = b4[tid], c5 = b5[tid];
#pragma unroll
    for (int r = 0; r < 8; r++) {
        int row = row0 + r, b = row / TT, t = row % TT;
        int o = (b * TT + t) * 128 + tid;
        g_PRE2[o] = p2[r] + c2;
        g_PRE3[o] = p3[r] + c3;
        g_PRE4[o] = p4[r] + c4;
        g_PRE5[o] = p5[r] + c5;
    }
}

// ---------------------------------------------------------------------------
// K3: the scan (HMMA bf16, SMEM frag buffers, no register bst)
// ---------------------------------------------------------------------------
#define O_HBF   0         // 18432: h bf16, frag-major, pitch 288 B/concept
#define O_WB    18432     // 32768: W4a B-fragments bf16
#define O_W5B   51200     // 65536
#define O_W2D   116736    // 16384 (swizzled)
#define O_W3D   133136    // 16384 (swizzled, +16B stagger)
#define O_W4B   149536    // 16384
#define O_PTB   165920    // 2048
#define O_PV    167968    // 512 comm
#define O_HT    168480    // 512 comm
#define O_CLG   168992    // 128 comm
#define O_HTLD  169120    // 512 (swizzled)
#define O_SV    169632    // 512
#define O_SLG   170144    // 512
#define O_Y4    170656    // 128
#define O_SE    170784    // 512 (e row)
#define SMEM_END 171296
static const unsigned SCAN_SMEM = SMEM_END + 1024;

__global__ void __cluster_dims__(4, 1, 1) __launch_bounds__(256, 1)
k_scan(const int* __restrict__ e_data, const float* __restrict__ q_matrix,
       const float* __restrict__ h0,
       const float* __restrict__ W4, const float* __restrict__ W5,
       const float* __restrict__ W2, const float* __restrict__ W3,
       float* __restrict__ out)
{
    extern __shared__ char smraw[];
    char* smb = (char*)(((uintptr_t)smraw + 1023) & ~(uintptr_t)1023);
    float* w5b   = (float*)(smb + O_W5B);
    float* w2d   = (float*)(smb + O_W2D);
    float* w3d   = (float*)(smb + O_W3D);
    float* w4b   = (float*)(smb + O_W4B);
    float* ptb   = (float*)(smb + O_PTB);
    float* comm_pv = (float*)(smb + O_PV);
    float* comm_ht = (float*)(smb + O_HT);
    float* comm_lg = (float*)(smb + O_CLG);
    float* htld  = (float*)(smb + O_HTLD);
    float* sv    = (float*)(smb + O_SV);
    float* sLG   = (float*)(smb + O_SLG);
    float* y4    = (float*)(smb + O_Y4);
    int*   se_sh = (int*)(smb + O_SE);

    const int tid  = threadIdx.x;
    const int wid  = tid >> 5;
    const int lane = tid & 31;
    const int g    = lane >> 2;
    const int t4   = lane & 3;
    const int wc   = wid & 3;
    const int jh   = wid >> 2;
    const int b    = blockIdx.x >> 2;
    const int rank = blockIdx.x & 3;
    const int c0   = rank * CS;
    const int cl_lo = wc * 16 + g;
    const int cl_hi = cl_lo + 8;
    cg::cluster_group cl = cg::this_cluster();

    // ---- fills ----
    for (int x = tid; x < 16384; x += 256)
        w5b[x] = W5[(128 + (x >> 7)) * 128 + (x & 127)];
    for (int x = tid; x < 4096; x += 256) {
        int i = x >> 5, jj = x & 31;
        int idx = i * 32 + (jj ^ ((i >> 5) << 3));
        w2d[idx] = W2[(384 + i) * 128 + rank * 32 + jj];
        w3d[idx] = W3[(384 + i) * 128 + rank * 32 + jj];
    }
    for (int x = tid; x < 1024; x += 256)
        ((float4*)w4b)[x] = ((const float4*)(W4 + 16384 + rank * 4096))[x];
    // W4a B-fragments
    for (int x = tid; x < 4096; x += 256) {
        int jt = x >> 8, ks = (x >> 5) & 7, l = x & 31;
        int j = jt * 8 + (l >> 2), k0 = ks * 16 + 2 * (l & 3);
        uint32_t b0 = packbf(W4[k0 * 128 + j], W4[(k0 + 1) * 128 + j]);
        uint32_t b1 = packbf(W4[(k0 + 8) * 128 + j], W4[(k0 + 9) * 128 + j]);
        *(uint2*)(smb + O_WB + x * 8) = make_uint2(b0, b1);
    }
    if (tid < 128) se_sh[tid] = e_data[b * SS + tid];

    // ---- h master regs + bf16 frag-major shadow ----
    float hreg[8][4];
#pragma unroll
    for (int nt = 0; nt < 8; nt++) {
        int j0 = jh * 64 + nt * 8 + 2 * t4;
        hreg[nt][0] = h0[(c0 + cl_lo) * 128 + j0];
        hreg[nt][1] = h0[(c0 + cl_lo) * 128 + j0 + 1];
        hreg[nt][2] = h0[(c0 + cl_hi) * 128 + j0];
        hreg[nt][3] = h0[(c0 + cl_hi) * 128 + j0 + 1];
    }
#pragma unroll
    for (int ntp = 0; ntp < 4; ntp++) {
        int ks = jh * 4 + ntp;
        *(uint2*)(smb + O_HBF + cl_lo * 288 + ks * 32 + t4 * 8) =
            make_uint2(packbf(hreg[2 * ntp][0], hreg[2 * ntp][1]),
                       packbf(hreg[2 * ntp + 1][0], hreg[2 * ntp + 1][1]));
        *(uint2*)(smb + O_HBF + cl_hi * 288 + ks * 32 + t4 * 8) =
            make_uint2(packbf(hreg[2 * ntp][2], hreg[2 * ntp][3]),
                       packbf(hreg[2 * ntp + 1][2], hreg[2 * ntp + 1][3]));
    }

    // ---- initial h_tilde ----
    {
        int e0 = e_data[b * SS];
        float qnl = q_matrix[e0 * 256 + c0 + cl_lo];
        float qnh = q_matrix[e0 * 256 + c0 + cl_hi];
        float ptp0[8], ptp1[8];
#pragma unroll
        for (int nt = 0; nt < 8; nt++) {
            ptp0[nt] = fmaf(qnl, hreg[nt][0], qnh * hreg[nt][2]);
            ptp1[nt] = fmaf(qnl, hreg[nt][1], qnh * hreg[nt][3]);
        }
#pragma unroll
        for (int nt = 0; nt < 8; nt++)
#pragma unroll
            for (int o = 16; o >= 4; o >>= 1) {
                ptp0[nt] += __shfl_down_sync(0xffffffffu, ptp0[nt], o);
                ptp1[nt] += __shfl_down_sync(0xffffffffu, ptp1[nt], o);
            }
        if (lane < 4) {
#pragma unroll
            for (int nt = 0; nt < 8; nt++)
                *(float2*)(ptb + wc * 128 + jh * 64 + nt * 8 + 2 * lane) =
                    make_float2(ptp0[nt], ptp1[nt]);
        }
    }
    __syncthreads();
    if (tid < 128) comm_ht[tid] = ptb[tid] + ptb[128 + tid] + ptb[256 + tid] + ptb[384 + tid];
    cl.sync();
    float* peer_ht[4];
    float* peer_pv[4];
    float* peer_lg[4];
#pragma unroll
    for (int r = 0; r < 4; r++) {
        peer_ht[r] = cl.map_shared_rank(comm_ht, r);
        peer_pv[r] = cl.map_shared_rank(comm_pv, r);
        peer_lg[r] = cl.map_shared_rank(comm_lg, r);
    }
    if (tid < 128)
        htld[hsw(tid)] = peer_ht[0][tid] + peer_ht[1][tid] + peer_ht[2][tid] + peer_ht[3][tid];
    __syncthreads();

    for (int t = 0; t < TT; t++) {
        const int base = (b * TT + t) * 128;
        int e = se_sh[t];
        int en = se_sh[t + 1];
        // ---- prefetch (LDG issued early) ----
        float qel = q_matrix[e * 256 + c0 + cl_lo];
        float qeh = q_matrix[e * 256 + c0 + cl_hi];
        float qnl = q_matrix[en * 256 + c0 + cl_lo];
        float qnh = q_matrix[en * 256 + c0 + cl_hi];
        float preA = 0.f;
        if ((tid & 3) == 0)
            preA = ((tid & 7) < 4) ? g_PRE2[base + rank * 32 + (tid >> 3)]
                                   : g_PRE3[base + rank * 32 + (tid >> 3)];
        float p4 = 0.f, p5 = 0.f;
        if (tid < 128) p4 = g_PRE4[base + tid];
        else if (t > 0) p5 = g_PRE5[(b * TT + t - 1) * 128 + (tid - 128)];

        // ---- GEMM first (operands stable from t-1); HMMA drains under GEMVs ----
        float dfr[8][4];
#pragma unroll
        for (int nt = 0; nt < 8; nt++) {
            dfr[nt][0] = 0.f; dfr[nt][1] = 0.f; dfr[nt][2] = 0.f; dfr[nt][3] = 0.f;
        }
#pragma unroll
        for (int ks = 0; ks < 8; ks++) {
            uint2 va = *(const uint2*)(smb + O_HBF + cl_lo * 288 + ks * 32 + t4 * 8);
            uint2 vb = *(const uint2*)(smb + O_HBF + cl_hi * 288 + ks * 32 + t4 * 8);
#pragma unroll
            for (int nt = 0; nt < 8; nt++) {
                uint2 bb = *(const uint2*)(smb + O_WB + (((jh * 8 + nt) * 8 + ks) * 64 + lane * 2) * 4);
                mma_bf16(dfr[nt], va.x, vb.x, va.y, vb.y, bb.x, bb.y);
            }
        }

        // ---- fused lg/gl GEMV + LG (8 threads per j) ----
        {
            int j = tid >> 3;
            int sub = tid & 7;
            int q = sub & 3;
            const float* Wd = (sub < 4) ? w2d : w3d;
            int wof = j ^ (q << 3);
            float s0 = 0.f, s1 = 0.f;
            int k0 = q * 32;
#pragma unroll
            for (int ii = 0; ii < 32; ii += 2) {
                int k = k0 + ii;
                s0 = fmaf(htld[k ^ (q << 3)], Wd[k * 32 + wof], s0);
                s1 = fmaf(htld[(k + 1) ^ (q << 3)], Wd[(k + 1) * 32 + wof], s1);
            }
            float s = s0 + s1;
            s += __shfl_down_sync(0xffffffffu, s, 2);
            s += __shfl_down_sync(0xffffffffu, s, 1);
            s += preA;   // pre2 at sub0, pre3 at sub4, 0 elsewhere
            float other = __shfl_down_sync(0xffffffffu, s, 4);
            if (sub == 0)
                comm_lg[j] = sigf(other) * (tanh_ap(s) + 1.f) * 0.5f;
        }
        __syncthreads();  // bar A: comm_lg ready

        if (tid < 128) {
            // partial v
            float s0 = 0.f, s1 = 0.f;
#pragma unroll
            for (int r = 0; r < 32; r += 2) {
                s0 = fmaf(comm_lg[r], w4b[r * 128 + tid], s0);
                s1 = fmaf(comm_lg[r + 1], w4b[(r + 1) * 128 + tid], s1);
            }
            comm_pv[tid] = s0 + s1;
        } else {
            // y(t-1), 4 accumulators
            int j = tid - 128;
            float a0 = 0.f, a1 = 0.f, a2 = 0.f, a3 = 0.f;
#pragma unroll
            for (int i = 0; i < 128; i += 4) {
                a0 = fmaf(htld[hsw(i)], w5b[i * 128 + j], a0);
                a1 = fmaf(htld[hsw(i + 1)], w5b[(i + 1) * 128 + j], a1);
                a2 = fmaf(htld[hsw(i + 2)], w5b[(i + 2) * 128 + j], a2);
                a3 = fmaf(htld[hsw(i + 3)], w5b[(i + 3) * 128 + j], a3);
            }
            float val = (t > 0) ? sigf(p5 + (a0 + a1) + (a2 + a3)) : 0.f;
#pragma unroll
            for (int o = 16; o > 0; o >>= 1) val += __shfl_down_sync(0xffffffffu, val, o);
            if (lane == 0) y4[wid - 4] = val;
        }
        cl.sync();  // #1: publish LG + partial v

        if (tid < 128) {
            float s = p4 + peer_pv[0][tid] + peer_pv[1][tid] + peer_pv[2][tid] + peer_pv[3][tid];
            sv[tid] = s;
            sLG[tid] = peer_lg[tid >> 5][tid & 31];
        }
        if (rank == 0 && tid == 0 && t > 0)
            out[b * SS + t] = (y4[0] + y4[1] + y4[2] + y4[3]) * (1.f / 128.f);
        __syncthreads();  // bar B: sv/sLG ready

        // ---- update ----
        {
            float ptp0[8], ptp1[8];
            uint32_t pklo[8], pkhi[8];
#pragma unroll
            for (int nt = 0; nt < 8; nt++) {
                int j0 = jh * 64 + nt * 8 + 2 * t4;
                float2 v2 = *(const float2*)(sv + j0);
                float2 l2 = *(const float2*)(sLG + j0);
                float g0 = sigf(dfr[nt][0] + v2.x);
                float g1 = sigf(dfr[nt][1] + v2.y);
                float g2 = sigf(dfr[nt][2] + v2.x);
                float g3 = sigf(dfr[nt][3] + v2.y);
                float h0n = fmaf(qel, l2.x, g0 * hreg[nt][0]);
                float h1n = fmaf(qel, l2.y, g1 * hreg[nt][1]);
                float h2n = fmaf(qeh, l2.x, g2 * hreg[nt][2]);
                float h3n = fmaf(qeh, l2.y, g3 * hreg[nt][3]);
                hreg[nt][0] = h0n; hreg[nt][1] = h1n;
                hreg[nt][2] = h2n; hreg[nt][3] = h3n;
                pklo[nt] = packbf(h0n, h1n);
                pkhi[nt] = packbf(h2n, h3n);
                ptp0[nt] = fmaf(qnl, h0n, qnh * h2n);
                ptp1[nt] = fmaf(qnl, h1n, qnh * h3n);
            }
#pragma unroll
            for (int ntp = 0; ntp < 4; ntp++) {
                int ks = jh * 4 + ntp;
                *(uint2*)(smb + O_HBF + cl_lo * 288 + ks * 32 + t4 * 8) =
                    make_uint2(pklo[2 * ntp], pklo[2 * ntp + 1]);
                *(uint2*)(smb + O_HBF + cl_hi * 288 + ks * 32 + t4 * 8) =
                    make_uint2(pkhi[2 * ntp], pkhi[2 * ntp + 1]);
            }
#pragma unroll
            for (int nt = 0; nt < 8; nt++)
#pragma unroll
                for (int o = 16; o >= 4; o >>= 1) {
                    ptp0[nt] += __shfl_down_sync(0xffffffffu, ptp0[nt], o);
                    ptp1[nt] += __shfl_down_sync(0xffffffffu, ptp1[nt], o);
                }
            if (lane < 4) {
#pragma unroll
                for (int nt = 0; nt < 8; nt++)
                    *(float2*)(ptb + wc * 128 + jh * 64 + nt * 8 + 2 * lane) =
                        make_float2(ptp0[nt], ptp1[nt]);
            }
        }
        __syncthreads();  // bar C: ptb ready
        if (tid < 128) comm_ht[tid] = ptb[tid] + ptb[128 + tid] + ptb[256 + tid] + ptb[384 + tid];
        cl.sync();  // #2: publish partial h_tilde
        if (tid < 128)
            htld[hsw(tid)] = peer_ht[0][tid] + peer_ht[1][tid] + peer_ht[2][tid] + peer_ht[3][tid];
        __syncthreads();  // bar D: htld + hbf ready for next step
    }

    // ---- final y ----
    if (tid >= 128) {
        int j = tid - 128;
        float p5 = g_PRE5[(b * TT + TT - 1) * 128 + j];
        float a0 = 0.f, a1 = 0.f, a2 = 0.f, a3 = 0.f;
#pragma unroll
        for (int i = 0; i < 128; i += 4) {
            a0 = fmaf(htld[hsw(i)], w5b[i * 128 + j], a0);
            a1 = fmaf(htld[hsw(i + 1)], w5b[(i + 1) * 128 + j], a1);
            a2 = fmaf(htld[hsw(i + 2)], w5b[(i + 2) * 128 + j], a2);
            a3 = fmaf(htld[hsw(i + 3)], w5b[(i + 3) * 128 + j], a3);
        }
        float val = sigf(p5 + (a0 + a1) + (a2 + a3));
#pragma unroll
        for (int o = 16; o > 0; o >>= 1) val += __shfl_down_sync(0xffffffffu, val, o);
        if (lane == 0) y4[wid - 4] = val;
    }
    __syncthreads();
    if (rank == 0 && tid == 0) {
        out[b * SS + SS - 1] = (y4[0] + y4[1] + y4[2] + y4[3]) * (1.f / 128.f);
        out[b * SS] = 0.f;
    }
}

extern "C" void kernel_launch(void* const* d_in, const int* in_sizes, int n_in,
                              void* d_out, int out_size)
{
    const int* e_data = (const int*)d_in[0];
    const int* at_data = (const int*)d_in[1];
    const int* it_data = (const int*)d_in[2];
    const float* a_data = (const float*)d_in[3];
    const float* q_matrix = (const float*)d_in[4];
    const float* e_E = (const float*)d_in[5];
    const float* at_E = (const float*)d_in[6];
    const float* it_E = (const float*)d_in[7];
    const float* W1 = (const float*)d_in[8];
    const float* b1 = (const float*)d_in[9];
    const float* W2 = (const float*)d_in[10];
    const float* b2 = (const float*)d_in[11];
    const float* W3 = (const float*)d_in[12];
    const float* b3 = (const float*)d_in[13];
    const float* W4 = (const float*)d_in[14];
    const float* b4 = (const float*)d_in[15];
    const float* W5 = (const float*)d_in[16];
    const float* b5 = (const float*)d_in[17];
    const float* h0 = (const float*)d_in[18];
    float* out = (float*)d_out;

    cudaFuncSetAttribute(k_scan, cudaFuncAttributeMaxDynamicSharedMemorySize, SCAN_SMEM);

    k_allearn<<<(BB * SS) / ATILE, 128>>>(e_data, at_data, a_data, e_E, at_E, W1, b1);
    k_pre<<<(BB * TT) / PTILE, 128>>>(e_data, it_data, it_E, e_E, W2, b2, W3, b3, W4, b4, W5, b5);
    k_scan<<<BB * 4, 256, SCAN_SMEM>>>(e_data, q_matrix, h0, W4, W5, W2, W3, out);
}

// round 17
// speedup vs baseline: 3.5420x; 1.2203x over previous
#include <cuda_runtime.h>
#include <cuda_bf16.h>
#include <cstdint>
#include <cooperative_groups.h>

namespace cg = cooperative_groups;

#define BB 32
#define SS 128
#define TT 127
#define CS 64
#define HPB 272   // hbf byte pitch per concept (68 words: <=2-way banks on frag loads)

__device__ float g_AL[BB * SS * 128];
__device__ float g_PRE2[BB * TT * 128];
__device__ float g_PRE3[BB * TT * 128];
__device__ float g_PRE4[BB * TT * 128];
__device__ float g_PRE5[BB * TT * 128];

__device__ __forceinline__ float tanh_ap(float x) {
    float y; asm("tanh.approx.f32 %0, %1;" : "=f"(y) : "f"(x)); return y;
}
__device__ __forceinline__ float sigf(float x) { return fmaf(0.5f, tanh_ap(0.5f * x), 0.5f); }
__device__ __forceinline__ uint32_t packbf(float lo, float hi) {
    uint32_t r; asm("cvt.rn.bf16x2.f32 %0, %1, %2;" : "=r"(r) : "f"(hi), "f"(lo)); return r;
}
__device__ __forceinline__ void mma_bf16(float* d, uint32_t a0, uint32_t a1, uint32_t a2,
                                         uint32_t a3, uint32_t b0, uint32_t b1) {
    asm volatile("mma.sync.aligned.m16n8k16.row.col.f32.bf16.bf16.f32 "
                 "{%0,%1,%2,%3}, {%4,%5,%6,%7}, {%8,%9}, {%0,%1,%2,%3};"
                 : "+f"(d[0]), "+f"(d[1]), "+f"(d[2]), "+f"(d[3])
                 : "r"(a0), "r"(a1), "r"(a2), "r"(a3), "r"(b0), "r"(b1));
}
__device__ __forceinline__ int hsw(int k) { return k ^ ((k >> 5) << 3); }

// ---------------------------------------------------------------------------
// K1: all_learning, 8 rows/block (grid 512: reuse AND occupancy)
// ---------------------------------------------------------------------------
#define ATILE 8
__global__ void k_allearn(const int* __restrict__ e_data, const int* __restrict__ at_data,
                          const float* __restrict__ a_data,
                          const float* __restrict__ e_E, const float* __restrict__ at_E,
                          const float* __restrict__ W1, const float* __restrict__ b1)
{
    __shared__ float se_t[128 * ATILE], sat_t[128 * ATILE];
    __shared__ float av[ATILE];
    __shared__ int ev[ATILE], atv[ATILE];
    int blk = blockIdx.x, tid = threadIdx.x;
    if (tid < ATILE) {
        int bs = blk * ATILE + tid;
        ev[tid] = e_data[bs]; atv[tid] = at_data[bs]; av[tid] = a_data[bs];
    }
    __syncthreads();
    for (int x = tid; x < ATILE * 128; x += 128) {
        int r = x >> 7, k = x & 127;
        se_t[k * ATILE + r] = e_E[ev[r] * 128 + k];
        sat_t[k * ATILE + r] = at_E[atv[r] * 128 + k];
    }
    __syncthreads();
    float acc[ATILE];
#pragma unroll
    for (int r = 0; r < ATILE; r++) acc[r] = 0.f;
    float cs = 0.f;
#pragma unroll 5
    for (int i = 0; i < 50; i++) cs += W1[(256 + i) * 128 + tid];
#pragma unroll 4
    for (int k = 0; k < 128; k++) {
        float w = W1[k * 128 + tid];
        float4 x0 = *(const float4*)&se_t[k * ATILE];
        float4 x1 = *(const float4*)&se_t[k * ATILE + 4];
        acc[0] = fmaf(x0.x, w, acc[0]); acc[1] = fmaf(x0.y, w, acc[1]);
        acc[2] = fmaf(x0.z, w, acc[2]); acc[3] = fmaf(x0.w, w, acc[3]);
        acc[4] = fmaf(x1.x, w, acc[4]); acc[5] = fmaf(x1.y, w, acc[5]);
        acc[6] = fmaf(x1.z, w, acc[6]); acc[7] = fmaf(x1.w, w, acc[7]);
    }
#pragma unroll 4
    for (int k = 0; k < 128; k++) {
        float w = W1[(128 + k) * 128 + tid];
        float4 x0 = *(const float4*)&sat_t[k * ATILE];
        float4 x1 = *(const float4*)&sat_t[k * ATILE + 4];
        acc[0] = fmaf(x0.x, w, acc[0]); acc[1] = fmaf(x0.y, w, acc[1]);
        acc[2] = fmaf(x0.z, w, acc[2]); acc[3] = fmaf(x0.w, w, acc[3]);
        acc[4] = fmaf(x1.x, w, acc[4]); acc[5] = fmaf(x1.y, w, acc[5]);
        acc[6] = fmaf(x1.z, w, acc[6]); acc[7] = fmaf(x1.w, w, acc[7]);
    }
    float bb = b1[tid];
#pragma unroll
    for (int r = 0; r < ATILE; r++)
        g_AL[(blk * ATILE + r) * 128 + tid] = acc[r] + fmaf(av[r], cs, bb);
}

// ---------------------------------------------------------------------------
// K2: precomputables, 8 (b,t) rows per block
// ---------------------------------------------------------------------------
#define PTILE 8
__global__ void k_pre(const int* __restrict__ e_data, const int* __restrict__ it_data,
                      const float* __restrict__ it_E, const float* __restrict__ e_E,
                      const float* __restrict__ W2, const float* __restrict__ b2,
                      const float* __restrict__ W3, const float* __restrict__ b3,
                      const float* __restrict__ W4, const float* __restrict__ b4,
                      const float* __restrict__ W5, const float* __restrict__ b5)
{
    __shared__ float xa[128 * PTILE], xb[128 * PTILE], xc[128 * PTILE], xd[128 * PTILE];
    __shared__ int itv[PTILE], env[PTILE];
    int blk = blockIdx.x, tid = threadIdx.x;
    int row0 = blk * PTILE;
    if (tid < PTILE) {
        int row = row0 + tid, b = row / TT, t = row % TT;
        itv[tid] = it_data[b * SS + t];
        env[tid] = e_data[b * SS + t + 1];
    }
    __syncthreads();
    for (int x = tid; x < 128 * PTILE; x += 128) {
        int r = x >> 7, k = x & 127;
        int row = row0 + r, b = row / TT, t = row % TT;
        xa[k * 8 + r] = (t > 0) ? g_AL[(b * SS + t - 1) * 128 + k] : 0.f;
        xc[k * 8 + r] = g_AL[(b * SS + t) * 128 + k];
        xb[k * 8 + r] = it_E[itv[r] * 128 + k];
        xd[k * 8 + r] = e_E[env[r] * 128 + k];
    }
    __syncthreads();
    float p2[8], p3[8], p4[8], p5[8];
#pragma unroll
    for (int r = 0; r < 8; r++) { p2[r] = 0.f; p3[r] = 0.f; p4[r] = 0.f; p5[r] = 0.f; }
#pragma unroll 2
    for (int k = 0; k < 128; k++) {
        float w2 = W2[k * 128 + tid], w3 = W3[k * 128 + tid];
        float4 x0 = *(const float4*)&xa[k * 8], x1 = *(const float4*)&xa[k * 8 + 4];
        float xs[8] = {x0.x, x0.y, x0.z, x0.w, x1.x, x1.y, x1.z, x1.w};
#pragma unroll
        for (int r = 0; r < 8; r++) { p2[r] = fmaf(xs[r], w2, p2[r]); p3[r] = fmaf(xs[r], w3, p3[r]); }
    }
#pragma unroll 2
    for (int k = 0; k < 128; k++) {
        float w2 = W2[(128 + k) * 128 + tid], w3 = W3[(128 + k) * 128 + tid];
        float w4 = W4[(256 + k) * 128 + tid];
        float4 x0 = *(const float4*)&xb[k * 8], x1 = *(const float4*)&xb[k * 8 + 4];
        float xs[8] = {x0.x, x0.y, x0.z, x0.w, x1.x, x1.y, x1.z, x1.w};
#pragma unroll
        for (int r = 0; r < 8; r++) {
            p2[r] = fmaf(xs[r], w2, p2[r]); p3[r] = fmaf(xs[r], w3, p3[r]);
            p4[r] = fmaf(xs[r], w4, p4[r]);
        }
    }
#pragma unroll 2
    for (int k = 0; k < 128; k++) {
        float w2 = W2[(256 + k) * 128 + tid], w3 = W3[(256 + k) * 128 + tid];
        float4 x0 = *(const float4*)&xc[k * 8], x1 = *(const float4*)&xc[k * 8 + 4];
        float xs[8] = {x0.x, x0.y, x0.z, x0.w, x1.x, x1.y, x1.z, x1.w};
#pragma unroll
        for (int r = 0; r < 8; r++) { p2[r] = fmaf(xs[r], w2, p2[r]); p3[r] = fmaf(xs[r], w3, p3[r]); }
    }
#pragma unroll 2
    for (int k = 0; k < 128; k++) {
        float w5 = W5[k * 128 + tid];
        float4 x0 = *(const float4*)&xd[k * 8], x1 = *(const float4*)&xd[k * 8 + 4];
        float xs[8] = {x0.x, x0.y, x0.z, x0.w, x1.x, x1.y, x1.z, x1.w};
#pragma unroll
        for (int r = 0; r < 8; r++) p5[r] = fmaf(xs[r], w5, p5[r]);
    }
    float c2 = b2[tid], c3 = b3[tid], c4 = b4[tid], c5 = b5[tid];
#pragma unroll
    for (int r = 0; r < 8; r++) {
        int row = row0 + r, b = row / TT, t = row % TT;
        int o = (b * TT + t) * 128 + tid;
        g_PRE2[o] = p2[r] + c2;
        g_PRE3[o] = p3[r] + c3;
        g_PRE4[o] = p4[r] + c4;
        g_PRE5[o] = p5[r] + c5;
    }
}

// ---------------------------------------------------------------------------
// K3: the scan
// ---------------------------------------------------------------------------
#define O_HBF   0         // 17408: h bf16, pitch HPB
#define O_WB    17408     // 32768: W4a B-fragments bf16
#define O_W5B   50176     // 16384: W5 rows 128..255, rank's 32-col slice (swizzled)
#define O_W2D   66560     // 16384 (swizzled)
#define O_W3D   82944     // 16384 (swizzled)
#define O_W4B   99328     // 16384
#define O_PTB   115712    // 2048
#define O_PV    117760    // 512 comm
#define O_HT    118272    // 512 comm
#define O_CLG   118784    // 128 comm
#define O_Y     118912    // 16  comm (y partial scalar)
#define O_HTLD  118928    // 512 (swizzled)
#define O_SV    119440    // 512
#define O_SLG   119952    // 512
#define O_Y4    120464    // 128
#define O_SE    120592    // 512
#define SMEM_END 121104
static const unsigned SCAN_SMEM = SMEM_END + 1024;

__global__ void __cluster_dims__(4, 1, 1) __launch_bounds__(256, 1)
k_scan(const int* __restrict__ e_data, const float* __restrict__ q_matrix,
       const float* __restrict__ h0,
       const float* __restrict__ W4, const float* __restrict__ W5,
       const float* __restrict__ W2, const float* __restrict__ W3,
       float* __restrict__ out)
{
    extern __shared__ char smraw[];
    char* smb = (char*)(((uintptr_t)smraw + 1023) & ~(uintptr_t)1023);
    float* w5b   = (float*)(smb + O_W5B);
    float* w2d   = (float*)(smb + O_W2D);
    float* w3d   = (float*)(smb + O_W3D);
    float* w4b   = (float*)(smb + O_W4B);
    float* ptb   = (float*)(smb + O_PTB);
    float* comm_pv = (float*)(smb + O_PV);
    float* comm_ht = (float*)(smb + O_HT);
    float* comm_lg = (float*)(smb + O_CLG);
    float* comm_y  = (float*)(smb + O_Y);
    float* htld  = (float*)(smb + O_HTLD);
    float* sv    = (float*)(smb + O_SV);
    float* sLG   = (float*)(smb + O_SLG);
    float* y4    = (float*)(smb + O_Y4);
    int*   se_sh = (int*)(smb + O_SE);

    const int tid  = threadIdx.x;
    const int wid  = tid >> 5;
    const int lane = tid & 31;
    const int g    = lane >> 2;
    const int t4   = lane & 3;
    const int wc   = wid & 3;
    const int jh   = wid >> 2;
    const int b    = blockIdx.x >> 2;
    const int rank = blockIdx.x & 3;
    const int c0   = rank * CS;
    const int cl_lo = wc * 16 + g;
    const int cl_hi = cl_lo + 8;
    cg::cluster_group cl = cg::this_cluster();

    // ---- fills ----
    for (int x = tid; x < 4096; x += 256) {
        int k = x >> 5, j = x & 31;
        w5b[k * 32 + (j ^ ((k >> 5) << 3))] = W5[(128 + k) * 128 + rank * 32 + j];
        w2d[k * 32 + (j ^ ((k >> 5) << 3))] = W2[(384 + k) * 128 + rank * 32 + j];
        w3d[k * 32 + (j ^ ((k >> 5) << 3))] = W3[(384 + k) * 128 + rank * 32 + j];
    }
    for (int x = tid; x < 1024; x += 256)
        ((float4*)w4b)[x] = ((const float4*)(W4 + 16384 + rank * 4096))[x];
    for (int x = tid; x < 4096; x += 256) {
        int jt = x >> 8, ks = (x >> 5) & 7, l = x & 31;
        int j = jt * 8 + (l >> 2), k0 = ks * 16 + 2 * (l & 3);
        uint32_t b0 = packbf(W4[k0 * 128 + j], W4[(k0 + 1) * 128 + j]);
        uint32_t b1 = packbf(W4[(k0 + 8) * 128 + j], W4[(k0 + 9) * 128 + j]);
        *(uint2*)(smb + O_WB + x * 8) = make_uint2(b0, b1);
    }
    if (tid < 128) se_sh[tid] = e_data[b * SS + tid];

    // ---- h master regs + bf16 shadow ----
    float hreg[8][4];
#pragma unroll
    for (int nt = 0; nt < 8; nt++) {
        int j0 = jh * 64 + nt * 8 + 2 * t4;
        hreg[nt][0] = h0[(c0 + cl_lo) * 128 + j0];
        hreg[nt][1] = h0[(c0 + cl_lo) * 128 + j0 + 1];
        hreg[nt][2] = h0[(c0 + cl_hi) * 128 + j0];
        hreg[nt][3] = h0[(c0 + cl_hi) * 128 + j0 + 1];
    }
#pragma unroll
    for (int ntp = 0; ntp < 4; ntp++) {
        int ks = jh * 4 + ntp;
        *(uint2*)(smb + O_HBF + cl_lo * HPB + ks * 32 + t4 * 8) =
            make_uint2(packbf(hreg[2 * ntp][0], hreg[2 * ntp][1]),
                       packbf(hreg[2 * ntp + 1][0], hreg[2 * ntp + 1][1]));
        *(uint2*)(smb + O_HBF + cl_hi * HPB + ks * 32 + t4 * 8) =
            make_uint2(packbf(hreg[2 * ntp][2], hreg[2 * ntp][3]),
                       packbf(hreg[2 * ntp + 1][2], hreg[2 * ntp + 1][3]));
    }

    // ---- initial h_tilde ----
    {
        int e0 = e_data[b * SS];
        float qnl = q_matrix[e0 * 256 + c0 + cl_lo];
        float qnh = q_matrix[e0 * 256 + c0 + cl_hi];
        float ptp0[8], ptp1[8];
#pragma unroll
        for (int nt = 0; nt < 8; nt++) {
            ptp0[nt] = fmaf(qnl, hreg[nt][0], qnh * hreg[nt][2]);
            ptp1[nt] = fmaf(qnl, hreg[nt][1], qnh * hreg[nt][3]);
        }
#pragma unroll
        for (int nt = 0; nt < 8; nt++)
#pragma unroll
            for (int o = 16; o >= 4; o >>= 1) {
                ptp0[nt] += __shfl_down_sync(0xffffffffu, ptp0[nt], o);
                ptp1[nt] += __shfl_down_sync(0xffffffffu, ptp1[nt], o);
            }
        if (lane < 4) {
#pragma unroll
            for (int nt = 0; nt < 8; nt++)
                *(float2*)(ptb + wc * 128 + jh * 64 + nt * 8 + 2 * lane) =
                    make_float2(ptp0[nt], ptp1[nt]);
        }
    }
    __syncthreads();
    if (tid < 128) comm_ht[tid] = ptb[tid] + ptb[128 + tid] + ptb[256 + tid] + ptb[384 + tid];
    cl.sync();
    float* peer_ht[4];
    float* peer_pv[4];
    float* peer_lg[4];
    float* peer_y[4];
#pragma unroll
    for (int r = 0; r < 4; r++) {
        peer_ht[r] = cl.map_shared_rank(comm_ht, r);
        peer_pv[r] = cl.map_shared_rank(comm_pv, r);
        peer_lg[r] = cl.map_shared_rank(comm_lg, r);
        peer_y[r]  = cl.map_shared_rank(comm_y, r);
    }
    if (tid < 128)
        htld[hsw(tid)] = peer_ht[0][tid] + peer_ht[1][tid] + peer_ht[2][tid] + peer_ht[3][tid];
    __syncthreads();

    for (int t = 0; t < TT; t++) {
        const int base = (b * TT + t) * 128;
        int e = se_sh[t];
        int en = se_sh[t + 1];
        // ---- prefetch ----
        float qel = q_matrix[e * 256 + c0 + cl_lo];
        float qeh = q_matrix[e * 256 + c0 + cl_hi];
        float qnl = q_matrix[en * 256 + c0 + cl_lo];
        float qnh = q_matrix[en * 256 + c0 + cl_hi];
        float preA2 = 0.f, preA3 = 0.f, p4 = 0.f, p5 = 0.f;
        if (tid < 128) {
            p4 = g_PRE4[base + tid];
            if ((tid & 3) == 0) {
                preA2 = g_PRE2[base + rank * 32 + (tid >> 2)];
                preA3 = g_PRE3[base + rank * 32 + (tid >> 2)];
            }
        } else if ((tid & 3) == 0 && t > 0) {
            p5 = g_PRE5[(b * TT + t - 1) * 128 + rank * 32 + ((tid - 128) >> 2)];
        }

        // ---- GEMM (operands from t-1, drains under GEMVs) ----
        float dfr[8][4];
#pragma unroll
        for (int nt = 0; nt < 8; nt++) {
            dfr[nt][0] = 0.f; dfr[nt][1] = 0.f; dfr[nt][2] = 0.f; dfr[nt][3] = 0.f;
        }
#pragma unroll
        for (int ks = 0; ks < 8; ks++) {
            uint2 va = *(const uint2*)(smb + O_HBF + cl_lo * HPB + ks * 32 + t4 * 8);
            uint2 vb = *(const uint2*)(smb + O_HBF + cl_hi * HPB + ks * 32 + t4 * 8);
#pragma unroll
            for (int nt = 0; nt < 8; nt++) {
                uint2 bb = *(const uint2*)(smb + O_WB + (((jh * 8 + nt) * 8 + ks) * 64 + lane * 2) * 4);
                mma_bf16(dfr[nt], va.x, vb.x, va.y, vb.y, bb.x, bb.y);
            }
        }

        // ---- phase 1: warps 0-3 lg/gl; warps 4-7 y-slice ----
        if (tid < 128) {
            int j = tid >> 2, q = tid & 3;
            int wof = j ^ (q << 3);
            float s2 = 0.f, s3 = 0.f;
            int k0 = q * 32;
#pragma unroll
            for (int i = 0; i < 32; i++) {
                int k = k0 + i;
                float hv = htld[k ^ (q << 3)];
                s2 = fmaf(hv, w2d[k * 32 + wof], s2);
                s3 = fmaf(hv, w3d[k * 32 + wof], s3);
            }
            s2 += __shfl_down_sync(0xffffffffu, s2, 2);
            s2 += __shfl_down_sync(0xffffffffu, s2, 1);
            s3 += __shfl_down_sync(0xffffffffu, s3, 2);
            s3 += __shfl_down_sync(0xffffffffu, s3, 1);
            if (q == 0)
                comm_lg[j] = sigf(s3 + preA3) * (tanh_ap(s2 + preA2) + 1.f) * 0.5f;
        } else {
            int jl = (tid - 128) >> 2, q = tid & 3;
            int wof = jl ^ (q << 3);
            float s = 0.f;
            int k0 = q * 32;
#pragma unroll
            for (int i = 0; i < 32; i++) {
                int k = k0 + i;
                s = fmaf(htld[k ^ (q << 3)], w5b[k * 32 + wof], s);
            }
            s += __shfl_down_sync(0xffffffffu, s, 2);
            s += __shfl_down_sync(0xffffffffu, s, 1);
            float val = (q == 0 && t > 0) ? sigf(p5 + s) : 0.f;
#pragma unroll
            for (int o = 16; o > 0; o >>= 1) val += __shfl_down_sync(0xffffffffu, val, o);
            if (lane == 0) y4[wid - 4] = val;
        }
        __syncthreads();  // bar A: comm_lg, y4 ready

        if (tid < 128) {
            float s0 = 0.f, s1 = 0.f;
#pragma unroll
            for (int r = 0; r < 32; r += 2) {
                s0 = fmaf(comm_lg[r], w4b[r * 128 + tid], s0);
                s1 = fmaf(comm_lg[r + 1], w4b[(r + 1) * 128 + tid], s1);
            }
            comm_pv[tid] = s0 + s1;
        } else if (tid == 128) {
            comm_y[0] = y4[0] + y4[1] + y4[2] + y4[3];
        }
        cl.sync();  // #1: publish LG, pv, y partial

        if (tid < 128) {
            float s = p4 + peer_pv[0][tid] + peer_pv[1][tid] + peer_pv[2][tid] + peer_pv[3][tid];
            sv[tid] = s;
            sLG[tid] = peer_lg[tid >> 5][tid & 31];
        }
        if (rank == 0 && tid == 0 && t > 0)
            out[b * SS + t] = (peer_y[0][0] + peer_y[1][0] + peer_y[2][0] + peer_y[3][0]) * (1.f / 128.f);
        __syncthreads();  // bar B: sv/sLG ready

        // ---- update ----
        {
            float ptp0[8], ptp1[8];
            uint32_t pklo[8], pkhi[8];
#pragma unroll
            for (int nt = 0; nt < 8; nt++) {
                int j0 = jh * 64 + nt * 8 + 2 * t4;
                float2 v2 = *(const float2*)(sv + j0);
                float2 l2 = *(const float2*)(sLG + j0);
                float g0 = sigf(dfr[nt][0] + v2.x);
                float g1 = sigf(dfr[nt][1] + v2.y);
                float g2 = sigf(dfr[nt][2] + v2.x);
                float g3 = sigf(dfr[nt][3] + v2.y);
                float h0n = fmaf(qel, l2.x, g0 * hreg[nt][0]);
                float h1n = fmaf(qel, l2.y, g1 * hreg[nt][1]);
                float h2n = fmaf(qeh, l2.x, g2 * hreg[nt][2]);
                float h3n = fmaf(qeh, l2.y, g3 * hreg[nt][3]);
                hreg[nt][0] = h0n; hreg[nt][1] = h1n;
                hreg[nt][2] = h2n; hreg[nt][3] = h3n;
                pklo[nt] = packbf(h0n, h1n);
                pkhi[nt] = packbf(h2n, h3n);
                ptp0[nt] = fmaf(qnl, h0n, qnh * h2n);
                ptp1[nt] = fmaf(qnl, h1n, qnh * h3n);
            }
#pragma unroll
            for (int ntp = 0; ntp < 4; ntp++) {
                int ks = jh * 4 + ntp;
                *(uint2*)(smb + O_HBF + cl_lo * HPB + ks * 32 + t4 * 8) =
                    make_uint2(pklo[2 * ntp], pklo[2 * ntp + 1]);
                *(uint2*)(smb + O_HBF + cl_hi * HPB + ks * 32 + t4 * 8) =
                    make_uint2(pkhi[2 * ntp], pkhi[2 * ntp + 1]);
            }
#pragma unroll
            for (int nt = 0; nt < 8; nt++)
#pragma unroll
                for (int o = 16; o >= 4; o >>= 1) {
                    ptp0[nt] += __shfl_down_sync(0xffffffffu, ptp0[nt], o);
                    ptp1[nt] += __shfl_down_sync(0xffffffffu, ptp1[nt], o);
                }
            if (lane < 4) {
#pragma unroll
                for (int nt = 0; nt < 8; nt++)
                    *(float2*)(ptb + wc * 128 + jh * 64 + nt * 8 + 2 * lane) =
                        make_float2(ptp0[nt], ptp1[nt]);
            }
        }
        __syncthreads();  // bar C: ptb ready
        if (tid < 128) comm_ht[tid] = ptb[tid] + ptb[128 + tid] + ptb[256 + tid] + ptb[384 + tid];
        cl.sync();  // #2: publish partial h_tilde
        if (tid < 128)
            htld[hsw(tid)] = peer_ht[0][tid] + peer_ht[1][tid] + peer_ht[2][tid] + peer_ht[3][tid];
        __syncthreads();  // bar D
    }

    // ---- final y (t = TT-1 -> pred[:, S-1]), sliced ----
    if (tid >= 128) {
        int jl = (tid - 128) >> 2, q = tid & 3;
        int wof = jl ^ (q << 3);
        float s = 0.f;
        int k0 = q * 32;
#pragma unroll
        for (int i = 0; i < 32; i++) {
            int k = k0 + i;
            s = fmaf(htld[k ^ (q << 3)], w5b[k * 32 + wof], s);
        }
        s += __shfl_down_sync(0xffffffffu, s, 2);
        s += __shfl_down_sync(0xffffffffu, s, 1);
        float val = 0.f;
        if (q == 0) {
            float p5f = g_PRE5[(b * TT + TT - 1) * 128 + rank * 32 + jl];
            val = sigf(p5f + s);
        }
#pragma unroll
        for (int o = 16; o > 0; o >>= 1) val += __shfl_down_sync(0xffffffffu, val, o);
        if (lane == 0) y4[wid - 4] = val;
    }
    __syncthreads();
    if (tid == 128) comm_y[0] = y4[0] + y4[1] + y4[2] + y4[3];
    cl.sync();
    if (rank == 0 && tid == 0) {
        out[b * SS + SS - 1] =
            (peer_y[0][0] + peer_y[1][0] + peer_y[2][0] + peer_y[3][0]) * (1.f / 128.f);
        out[b * SS] = 0.f;
    }
    // Exit-liveness fence: no CTA may exit while rank 0's DSMEM reads of
    // peer comm_y are potentially in flight. Rank 0's loads feed the global
    // store above, which precedes its barrier arrival in program order.
    cl.sync();
}

extern "C" void kernel_launch(void* const* d_in, const int* in_sizes, int n_in,
                              void* d_out, int out_size)
{
    const int* e_data = (const int*)d_in[0];
    const int* at_data = (const int*)d_in[1];
    const int* it_data = (const int*)d_in[2];
    const float* a_data = (const float*)d_in[3];
    const float* q_matrix = (const float*)d_in[4];
    const float* e_E = (const float*)d_in[5];
    const float* at_E = (const float*)d_in[6];
    const float* it_E = (const float*)d_in[7];
    const float* W1 = (const float*)d_in[8];
    const float* b1 = (const float*)d_in[9];
    const float* W2 = (const float*)d_in[10];
    const float* b2 = (const float*)d_in[11];
    const float* W3 = (const float*)d_in[12];
    const float* b3 = (const float*)d_in[13];
    const float* W4 = (const float*)d_in[14];
    const float* b4 = (const float*)d_in[15];
    const float* W5 = (const float*)d_in[16];
    const float* b5 = (const float*)d_in[17];
    const float* h0 = (const float*)d_in[18];
    float* out = (float*)d_out;

    cudaFuncSetAttribute(k_scan, cudaFuncAttributeMaxDynamicSharedMemorySize, SCAN_SMEM);

    k_allearn<<<(BB * SS) / ATILE, 128>>>(e_data, at_data, a_data, e_E, at_E, W1, b1);
    k_pre<<<(BB * TT) / PTILE, 128>>>(e_data, it_data, it_E, e_E, W2, b2, W3, b3, W4, b4, W5, b5);
    k_scan<<<BB * 4, 256, SCAN_SMEM>>>(e_data, q_matrix, h0, W4, W5, W2, W3, out);
}